// round 10
// baseline (speedup 1.0000x reference)
#include <cuda_runtime.h>
#include <cstdint>

// EdgeUpdate via mma.sync.m16n8k8.tf32, 512 threads = TWO independent 256-thread
// halves (named barriers), each on its own 64-edge x 128-out tile.
// Per half: 8 warps = 2 m-bands x 4 n-bands, 2x4 mma tiles each.
// GEMM1: K=256, 4 chunks of 64k through per-half pair buffer [32 pr][68] uint2.
// GEMM2: K=128, 2 rounds of 64k, h1 repacked to (k,k+4) pairs via shfl.
#define THREADS 512
#define NT2     10000         // 640000 / 64
#define PXS     68            // uint2 row stride (68 mod 16 = 4 -> conflict-free LDS.64)
#define HB      17408         // per-half buffer bytes = 32*PXS*8

// smem byte offsets
#define OW1 0                 // uint2 [128 pr][128 n] : 131072 B
#define OW2 131072            // uint2 [ 64 pr][128 n] :  65536 B
#define OX  196608            // 2 x per-half buffer (px / h1-pairs / red)
#define SMEM_BYTES (OX + 2 * HB)   // 231424

__device__ __forceinline__ unsigned tf32r(float x) {
  unsigned r; asm("cvt.rna.tf32.f32 %0, %1;" : "=r"(r) : "f"(x)); return r;
}
__device__ __forceinline__ float silu_f(float x) {
  return x * (1.0f / (1.0f + __expf(-x)));
}
__device__ __forceinline__ void mma8(float* d, unsigned a0, unsigned a1,
                                     unsigned a2, unsigned a3,
                                     unsigned b0, unsigned b1) {
  asm volatile("mma.sync.aligned.m16n8k8.row.col.f32.tf32.tf32.f32 "
    "{%0,%1,%2,%3}, {%4,%5,%6,%7}, {%8,%9}, {%0,%1,%2,%3};"
    : "+f"(d[0]), "+f"(d[1]), "+f"(d[2]), "+f"(d[3])
    : "r"(a0), "r"(a1), "r"(a2), "r"(a3), "r"(b0), "r"(b1));
}

__global__ void __launch_bounds__(THREADS, 1)
edge_update_mma5(const float* __restrict__ nodes,
                 const float* __restrict__ efeat,
                 const int*   __restrict__ srcI,
                 const int*   __restrict__ dstI,
                 const float* __restrict__ W1,
                 const float* __restrict__ b1,
                 const float* __restrict__ W2,
                 const float* __restrict__ b2,
                 const float* __restrict__ gamma,
                 const float* __restrict__ beta,
                 float* __restrict__ out)
{
  extern __shared__ char smem[];
  uint2* w1p = (uint2*)(smem + OW1);
  uint2* w2p = (uint2*)(smem + OW2);

  const int tid = threadIdx.x;

  // ---- stage weights as (k, k+4) tf32 pairs, swizzled n ^ ((pr&3)<<2) ----
  for (int i = tid; i < 16384; i += THREADS) {
    int pr = i >> 7, n = i & 127;
    int k0 = (pr >> 2) * 8 + (pr & 3);
    w1p[pr * 128 + (n ^ ((pr & 3) << 2))] =
        make_uint2(tf32r(W1[k0 * 128 + n]), tf32r(W1[(k0 + 4) * 128 + n]));
  }
  for (int i = tid; i < 8192; i += THREADS) {
    int pr = i >> 7, n = i & 127;
    int k0 = (pr >> 2) * 8 + (pr & 3);
    w2p[pr * 128 + (n ^ ((pr & 3) << 2))] =
        make_uint2(tf32r(W2[k0 * 128 + n]), tf32r(W2[(k0 + 4) * 128 + n]));
  }
  __syncthreads();   // last block-wide barrier; halves are independent below

  const int h    = tid >> 8;            // half 0/1
  const int htid = tid & 255;
  const int hw   = (tid >> 5) & 7;      // warp within half
  const int lane = tid & 31;
  const int kl = lane & 3, r = lane >> 2;
  const int mi = hw >> 2;               // edges [32*mi, 32*mi+32) of 64-edge tile
  const int nj = hw & 3;                // outs  [32*nj, 32*nj+32)
  const int mbase = mi * 32, nbase = nj * 32;
  const int e_loc = htid & 63, q4 = htid >> 6;    // fill mapping
  uint2* pxh = (uint2*)(smem + OX + h * HB);
  const int barid = 1 + h;
#define HBAR() asm volatile("bar.sync %0, 256;" :: "r"(barid) : "memory")

  // persistent bias registers (R7-proven; gamma/beta via __ldg at tail)
  float b1v[4][2], b2v[4][2];
#pragma unroll
  for (int u = 0; u < 4; u++) {
    int n = nbase + u * 8 + 2 * kl;
    b1v[u][0] = b1[n]; b1v[u][1] = b1[n + 1];
    b2v[u][0] = b2[n]; b2v[u][1] = b2[n + 1];
  }

  for (int tile = blockIdx.x * 2 + h; tile < NT2; tile += gridDim.x * 2) {
    const int e0 = tile * 64;
    const size_t si = (size_t)srcI[e0 + e_loc] * 64;
    const size_t di = (size_t)dstI[e0 + e_loc] * 64;
    HBAR();   // previous tile's epilogue buffer reads complete

    // ================= GEMM1: D1 = X[64,256] @ W1 =================
    float d1[2][4][4];
#pragma unroll
    for (int t = 0; t < 2; t++)
#pragma unroll
      for (int u = 0; u < 4; u++)
#pragma unroll
        for (int j = 0; j < 4; j++) d1[t][u][j] = 0.f;

#pragma unroll 1
    for (int c = 0; c < 4; c++) {
      // fill 64-k chunk c -> pairs [32 pr][e] (raw fp32 bits)
      {
        const float* base;
        if (c == 0)      base = nodes + si;
        else if (c == 1) base = nodes + di;
        else             base = efeat + (size_t)(e0 + e_loc) * 128 + (c - 2) * 64;
#pragma unroll
        for (int gg = 0; gg < 2; gg++) {
          int g = q4 * 2 + gg;
          float4 v0 = ((const float4*)(base + g * 8))[0];
          float4 v1 = ((const float4*)(base + g * 8))[1];
          pxh[(4 * g + 0) * PXS + e_loc] = make_uint2(__float_as_uint(v0.x), __float_as_uint(v1.x));
          pxh[(4 * g + 1) * PXS + e_loc] = make_uint2(__float_as_uint(v0.y), __float_as_uint(v1.y));
          pxh[(4 * g + 2) * PXS + e_loc] = make_uint2(__float_as_uint(v0.z), __float_as_uint(v1.z));
          pxh[(4 * g + 3) * PXS + e_loc] = make_uint2(__float_as_uint(v0.w), __float_as_uint(v1.w));
        }
      }
      HBAR();

      const int prc = c * 32;
#pragma unroll
      for (int k8 = 0; k8 < 8; k8++) {
        const int prb = k8 * 4 + kl;
        uint2 a0[2], a1[2], bb[4];
#pragma unroll
        for (int t = 0; t < 2; t++) {
          int m = mbase + t * 16 + r;
          a0[t] = pxh[prb * PXS + m];
          a1[t] = pxh[prb * PXS + m + 8];
        }
#pragma unroll
        for (int u = 0; u < 4; u++) {
          int n = nbase + u * 8 + r;
          bb[u] = w1p[(prc + prb) * 128 + (n ^ (kl << 2))];
        }
#pragma unroll
        for (int t = 0; t < 2; t++)
#pragma unroll
          for (int u = 0; u < 4; u++)
            mma8(d1[t][u], a0[t].x, a1[t].x, a0[t].y, a1[t].y, bb[u].x, bb[u].y);
      }
      HBAR();   // reads done before next fill / h1 store
    }

    // ---- h1 = silu(D1 + b1), raw fp32 bits ----
    unsigned h1f[2][4][4];
#pragma unroll
    for (int t = 0; t < 2; t++)
#pragma unroll
      for (int u = 0; u < 4; u++) {
        h1f[t][u][0] = __float_as_uint(silu_f(d1[t][u][0] + b1v[u][0]));
        h1f[t][u][1] = __float_as_uint(silu_f(d1[t][u][1] + b1v[u][1]));
        h1f[t][u][2] = __float_as_uint(silu_f(d1[t][u][2] + b1v[u][0]));
        h1f[t][u][3] = __float_as_uint(silu_f(d1[t][u][3] + b1v[u][1]));
      }

    // ================= GEMM2: D2 = H1[64,128] @ W2 =================
    float d2[2][4][4];
#pragma unroll
    for (int t = 0; t < 2; t++)
#pragma unroll
      for (int u = 0; u < 4; u++)
#pragma unroll
        for (int j = 0; j < 4; j++) d2[t][u][j] = 0.f;

#pragma unroll 1
    for (int c2 = 0; c2 < 2; c2++) {
      // warps whose n-band falls in this 64-k round store h1 as (k,k+4) pairs
      if ((nj >> 1) == c2) {
#pragma unroll
        for (int t = 0; t < 2; t++)
#pragma unroll
          for (int u = 0; u < 4; u++) {
            unsigned p0 = __shfl_xor_sync(0xffffffffu, h1f[t][u][0], 2);
            unsigned p1 = __shfl_xor_sync(0xffffffffu, h1f[t][u][1], 2);
            unsigned p2 = __shfl_xor_sync(0xffffffffu, h1f[t][u][2], 2);
            unsigned p3 = __shfl_xor_sync(0xffffffffu, h1f[t][u][3], 2);
            if (kl < 2) {
              int ka = (nj & 1) * 32 + u * 8 + 2 * kl;   // local k of this round
              int pra = (ka >> 3) * 4 + (ka & 7);        // pair row (ka&7 in {0,2})
              int m = mbase + t * 16 + r;
              pxh[pra * PXS + m]           = make_uint2(h1f[t][u][0], p0);
              pxh[pra * PXS + m + 8]       = make_uint2(h1f[t][u][2], p2);
              pxh[(pra + 1) * PXS + m]     = make_uint2(h1f[t][u][1], p1);
              pxh[(pra + 1) * PXS + m + 8] = make_uint2(h1f[t][u][3], p3);
            }
          }
      }
      HBAR();

      const int prc = c2 * 32;
#pragma unroll
      for (int k8 = 0; k8 < 8; k8++) {
        const int prb = k8 * 4 + kl;
        uint2 a0[2], a1[2], bb[4];
#pragma unroll
        for (int t = 0; t < 2; t++) {
          int m = mbase + t * 16 + r;
          a0[t] = pxh[prb * PXS + m];
          a1[t] = pxh[prb * PXS + m + 8];
        }
#pragma unroll
        for (int u = 0; u < 4; u++) {
          int n = nbase + u * 8 + r;
          bb[u] = w2p[(prc + prb) * 128 + (n ^ (kl << 2))];
        }
#pragma unroll
        for (int t = 0; t < 2; t++)
#pragma unroll
          for (int u = 0; u < 4; u++)
            mma8(d2[t][u], a0[t].x, a1[t].x, a0[t].y, a1[t].y, bb[u].x, bb[u].y);
      }
      HBAR();   // round reads done before next store / red overlay
    }

    // ================= epilogue: y = efeat + silu(D2+b2); LN =================
    float y[2][4][4];
    float s0[2], q0[2], s1[2], q1[2];
#pragma unroll
    for (int t = 0; t < 2; t++) { s0[t] = q0[t] = s1[t] = q1[t] = 0.f; }
#pragma unroll
    for (int t = 0; t < 2; t++) {
      int m = mbase + t * 16 + r;
#pragma unroll
      for (int u = 0; u < 4; u++) {
        int n = nbase + u * 8 + 2 * kl;
        float2 ef0 = *(const float2*)(efeat + (size_t)(e0 + m) * 128 + n);
        float2 ef1 = *(const float2*)(efeat + (size_t)(e0 + m + 8) * 128 + n);
        float v0 = ef0.x + silu_f(d2[t][u][0] + b2v[u][0]);
        float v1 = ef0.y + silu_f(d2[t][u][1] + b2v[u][1]);
        float v2 = ef1.x + silu_f(d2[t][u][2] + b2v[u][0]);
        float v3 = ef1.y + silu_f(d2[t][u][3] + b2v[u][1]);
        y[t][u][0] = v0; y[t][u][1] = v1; y[t][u][2] = v2; y[t][u][3] = v3;
        s0[t] += v0 + v1; q0[t] += v0 * v0 + v1 * v1;
        s1[t] += v2 + v3; q1[t] += v2 * v2 + v3 * v3;
      }
    }
#pragma unroll
    for (int t = 0; t < 2; t++) {
#pragma unroll
      for (int off = 1; off <= 2; off <<= 1) {
        s0[t] += __shfl_xor_sync(0xffffffffu, s0[t], off);
        q0[t] += __shfl_xor_sync(0xffffffffu, q0[t], off);
        s1[t] += __shfl_xor_sync(0xffffffffu, s1[t], off);
        q1[t] += __shfl_xor_sync(0xffffffffu, q1[t], off);
      }
    }
    // cross-warp LN combine through per-half smem (free after last HBAR)
    float2* red = (float2*)pxh;   // [4 nj][64 m]
    if (kl == 0) {
#pragma unroll
      for (int t = 0; t < 2; t++) {
        int m = mbase + t * 16 + r;
        red[nj * 64 + m]     = make_float2(s0[t], q0[t]);
        red[nj * 64 + m + 8] = make_float2(s1[t], q1[t]);
      }
    }
    HBAR();
#pragma unroll
    for (int t = 0; t < 2; t++) {
      int m = mbase + t * 16 + r;
      float S0 = 0.f, Q0 = 0.f, S1 = 0.f, Q1 = 0.f;
#pragma unroll
      for (int qd = 0; qd < 4; qd++) {
        float2 v = red[qd * 64 + m];     S0 += v.x; Q0 += v.y;
        float2 w = red[qd * 64 + m + 8]; S1 += w.x; Q1 += w.y;
      }
      float mean0 = S0 * 0.0078125f;
      float var0  = Q0 * 0.0078125f - mean0 * mean0;
      float rs0   = rsqrtf(var0 + 1e-5f);
      float mean1 = S1 * 0.0078125f;
      float var1  = Q1 * 0.0078125f - mean1 * mean1;
      float rs1   = rsqrtf(var1 + 1e-5f);
#pragma unroll
      for (int u = 0; u < 4; u++) {
        int n = nbase + u * 8 + 2 * kl;
        float g0 = __ldg(&gamma[n]), g1 = __ldg(&gamma[n + 1]);
        float t0 = __ldg(&beta[n]),  t1 = __ldg(&beta[n + 1]);
        float2 o0, o1;
        o0.x = (y[t][u][0] - mean0) * rs0 * g0 + t0;
        o0.y = (y[t][u][1] - mean0) * rs0 * g1 + t1;
        o1.x = (y[t][u][2] - mean1) * rs1 * g0 + t0;
        o1.y = (y[t][u][3] - mean1) * rs1 * g1 + t1;
        *(float2*)(out + (size_t)(e0 + m) * 128 + n)     = o0;
        *(float2*)(out + (size_t)(e0 + m + 8) * 128 + n) = o1;
      }
    }
    // next tile's top HBAR orders red reuse
  }
#undef HBAR
}

extern "C" void kernel_launch(void* const* d_in, const int* in_sizes, int n_in,
                              void* d_out, int out_size) {
  const float* nodes = (const float*)d_in[0];
  const float* efeat = (const float*)d_in[1];
  const int*   srcI  = (const int*)d_in[2];
  const int*   dstI  = (const int*)d_in[3];
  const float* W1    = (const float*)d_in[4];
  const float* b1    = (const float*)d_in[5];
  const float* W2    = (const float*)d_in[6];
  const float* b2    = (const float*)d_in[7];
  const float* gamma = (const float*)d_in[8];
  const float* beta  = (const float*)d_in[9];
  float* out = (float*)d_out;

  cudaFuncSetAttribute(edge_update_mma5,
                       cudaFuncAttributeMaxDynamicSharedMemorySize, SMEM_BYTES);
  int sms = 148;
  cudaDeviceGetAttribute(&sms, cudaDevAttrMultiProcessorCount, 0);
  if (sms < 1) sms = 148;

  edge_update_mma5<<<sms, THREADS, SMEM_BYTES>>>(
      nodes, efeat, srcI, dstI, W1, b1, W2, b2, gamma, beta, out);
}

// round 12
// speedup vs baseline: 1.0541x; 1.0541x over previous
#include <cuda_runtime.h>
#include <cstdint>

// EdgeUpdate via mma.sync.m16n8k8.tf32, 512 threads / 16 warps (R7 structure).
// GEMM1 operands quad-packed (k,k+4,k+8,k+12): one LDS.128 feeds two k8 steps.
// GEMM2 unchanged from R7 (848us measurement).
#define THREADS 512
#define NTILES  5000          // 640000 / 128
#define XQS     130           // uint4 row stride, x-quad buffer (130 mod 8 = 2)
#define HSTRIDE 136           // unpacked h1 stride (floats)

// smem byte offsets
#define OW1 0                 // uint4 [64 qr][128 n]  : 131072 B
#define OW2 131072            // uint2 [64 pr][128 n]  :  65536 B
#define OX  196608            // x quads (33280 B) / h1 (34816 B) / red
#define SMEM_BYTES (196608 + 64 * HSTRIDE * 4)   // 231424

__device__ __forceinline__ unsigned tf32r(float x) {
  unsigned r; asm("cvt.rna.tf32.f32 %0, %1;" : "=r"(r) : "f"(x)); return r;
}
__device__ __forceinline__ float silu_f(float x) {
  return x * (1.0f / (1.0f + __expf(-x)));
}
__device__ __forceinline__ void mma8(float* d, unsigned a0, unsigned a1,
                                     unsigned a2, unsigned a3,
                                     unsigned b0, unsigned b1) {
  asm volatile("mma.sync.aligned.m16n8k8.row.col.f32.tf32.tf32.f32 "
    "{%0,%1,%2,%3}, {%4,%5,%6,%7}, {%8,%9}, {%0,%1,%2,%3};"
    : "+f"(d[0]), "+f"(d[1]), "+f"(d[2]), "+f"(d[3])
    : "r"(a0), "r"(a1), "r"(a2), "r"(a3), "r"(b0), "r"(b1));
}

__global__ void __launch_bounds__(THREADS, 1)
edge_update_mma6(const float* __restrict__ nodes,
                 const float* __restrict__ efeat,
                 const int*   __restrict__ srcI,
                 const int*   __restrict__ dstI,
                 const float* __restrict__ W1,
                 const float* __restrict__ b1,
                 const float* __restrict__ W2,
                 const float* __restrict__ b2,
                 const float* __restrict__ gamma,
                 const float* __restrict__ beta,
                 float* __restrict__ out)
{
  extern __shared__ char smem[];
  uint4* w1q = (uint4*)(smem + OW1);
  uint2* w2p = (uint2*)(smem + OW2);
  uint4* xq  = (uint4*)(smem + OX);          // [16 qr][XQS] quads (GEMM1)
  unsigned* sxu = (unsigned*)(smem + OX);    // [64 k][HSTRIDE] unpacked h1 (GEMM2)

  const int tid  = threadIdx.x;
  const int warp = tid >> 5, lane = tid & 31;
  const int kl = lane & 3, r = lane >> 2;
  const int mi = warp >> 2;            // edges [32*mi, 32*mi+32)
  const int nj = warp & 3;             // outs  [32*nj, 32*nj+32)
  const int mbase = mi * 32;
  const int nbase = nj * 32;

  // ---- stage W1 as (k,k+4,k+8,k+12) quads, swizzled n ^ ((qr&3)<<1) ----
  for (int i = tid; i < 8192; i += THREADS) {     // 64 qr x 128 n
    int qr = i >> 7, n = i & 127;
    int k0 = (qr >> 2) * 16 + (qr & 3);
    w1q[qr * 128 + (n ^ ((qr & 3) << 1))] = make_uint4(
        tf32r(W1[k0 * 128 + n]),        tf32r(W1[(k0 + 4) * 128 + n]),
        tf32r(W1[(k0 + 8) * 128 + n]),  tf32r(W1[(k0 + 12) * 128 + n]));
  }
  // ---- stage W2 as (k,k+4) pairs, swizzled n ^ ((pr&3)<<2)  (R7 format) ----
  for (int i = tid; i < 8192; i += THREADS) {
    int pr = i >> 7, n = i & 127;
    int k0 = (pr >> 2) * 8 + (pr & 3);
    w2p[pr * 128 + (n ^ ((pr & 3) << 2))] =
        make_uint2(tf32r(W2[k0 * 128 + n]), tf32r(W2[(k0 + 4) * 128 + n]));
  }
  // persistent bias/affine registers (R7-proven)
  float b1v[4][2], b2v[4][2], gv[4][2], btv[4][2];
#pragma unroll
  for (int u = 0; u < 4; u++) {
    int n = nbase + u * 8 + 2 * kl;
    b1v[u][0] = b1[n];    b1v[u][1] = b1[n + 1];
    b2v[u][0] = b2[n];    b2v[u][1] = b2[n + 1];
    gv[u][0]  = gamma[n]; gv[u][1]  = gamma[n + 1];
    btv[u][0] = beta[n];  btv[u][1] = beta[n + 1];
  }
  __syncthreads();

  for (int tile = blockIdx.x; tile < NTILES; tile += gridDim.x) {
    const int e0 = tile * 128;

    // ================= GEMM1: D1 = X[128,256] @ W1 =================
    float d1[2][4][4];
#pragma unroll
    for (int t = 0; t < 2; t++)
#pragma unroll
      for (int u = 0; u < 4; u++)
#pragma unroll
        for (int j = 0; j < 4; j++) d1[t][u][j] = 0.f;

#pragma unroll 1
    for (int c = 0; c < 4; c++) {
      __syncthreads();   // previous xq use complete
      // gather 64-k chunk c -> quads [16 qr][e] (raw fp32 bits)
      {
        const int e = tid & 127, q4 = tid >> 7;   // q4: 16-k group
        const float* base;
        if (c == 0)      base = nodes + (size_t)srcI[e0 + e] * 64;
        else if (c == 1) base = nodes + (size_t)dstI[e0 + e] * 64;
        else             base = efeat + (size_t)(e0 + e) * 128 + (c - 2) * 64;
        const float4* b4 = (const float4*)(base + q4 * 16);
        float4 f0 = b4[0], f1 = b4[1], f2 = b4[2], f3 = b4[3];
        uint4* row = xq + (q4 * 4) * XQS + e;
        row[0]       = make_uint4(__float_as_uint(f0.x), __float_as_uint(f1.x),
                                  __float_as_uint(f2.x), __float_as_uint(f3.x));
        row[XQS]     = make_uint4(__float_as_uint(f0.y), __float_as_uint(f1.y),
                                  __float_as_uint(f2.y), __float_as_uint(f3.y));
        row[2 * XQS] = make_uint4(__float_as_uint(f0.z), __float_as_uint(f1.z),
                                  __float_as_uint(f2.z), __float_as_uint(f3.z));
        row[3 * XQS] = make_uint4(__float_as_uint(f0.w), __float_as_uint(f1.w),
                                  __float_as_uint(f2.w), __float_as_uint(f3.w));
      }
      __syncthreads();

      const int qc = c * 16;   // W1 quad-row offset of this chunk
#pragma unroll
      for (int p = 0; p < 4; p++) {          // 4 k8-pairs (16 k each)
        const int xr = p * 4 + kl;
        uint4 aA[2], aB[2], bq[4];
#pragma unroll
        for (int t = 0; t < 2; t++) {
          int m = mbase + t * 16 + r;
          aA[t] = xq[xr * XQS + m];
          aB[t] = xq[xr * XQS + m + 8];
        }
#pragma unroll
        for (int u = 0; u < 4; u++) {
          int n = nbase + u * 8 + r;
          bq[u] = w1q[(qc + xr) * 128 + (n ^ (kl << 1))];
        }
#pragma unroll
        for (int t = 0; t < 2; t++)
#pragma unroll
          for (int u = 0; u < 4; u++) {
            mma8(d1[t][u], aA[t].x, aB[t].x, aA[t].y, aB[t].y, bq[u].x, bq[u].y);
            mma8(d1[t][u], aA[t].z, aB[t].z, aA[t].w, aB[t].w, bq[u].z, bq[u].w);
          }
      }
    }

    // ---- h1 = silu(D1 + b1), raw fp32 bits ----
    unsigned h1f[2][4][4];
#pragma unroll
    for (int t = 0; t < 2; t++)
#pragma unroll
      for (int u = 0; u < 4; u++) {
        h1f[t][u][0] = __float_as_uint(silu_f(d1[t][u][0] + b1v[u][0]));
        h1f[t][u][1] = __float_as_uint(silu_f(d1[t][u][1] + b1v[u][1]));
        h1f[t][u][2] = __float_as_uint(silu_f(d1[t][u][2] + b1v[u][0]));
        h1f[t][u][3] = __float_as_uint(silu_f(d1[t][u][3] + b1v[u][1]));
      }

    // ================= GEMM2: D2 = H1[128,128] @ W2 (R7 verbatim) ==========
    float d2[2][4][4];
#pragma unroll
    for (int t = 0; t < 2; t++)
#pragma unroll
      for (int u = 0; u < 4; u++)
#pragma unroll
        for (int j = 0; j < 4; j++) d2[t][u][j] = 0.f;

#pragma unroll 1
    for (int c2 = 0; c2 < 2; c2++) {
      __syncthreads();   // xq/sxu reads done
      if ((nj >> 1) == c2) {
        const int kloc0 = (nj & 1) * 32;
#pragma unroll
        for (int t = 0; t < 2; t++)
#pragma unroll
          for (int u = 0; u < 4; u++) {
            int m = mbase + t * 16 + r;
            int kk = kloc0 + u * 8 + 2 * kl;
            sxu[kk * HSTRIDE + m]           = h1f[t][u][0];
            sxu[(kk + 1) * HSTRIDE + m]     = h1f[t][u][1];
            sxu[kk * HSTRIDE + m + 8]       = h1f[t][u][2];
            sxu[(kk + 1) * HSTRIDE + m + 8] = h1f[t][u][3];
          }
      }
      __syncthreads();

      const int prc = c2 * 32;
#pragma unroll
      for (int k8 = 0; k8 < 8; k8++) {
        const int kb = k8 * 8;
        unsigned a[2][4];
        uint2 bb[4];
#pragma unroll
        for (int t = 0; t < 2; t++) {
          int m = mbase + t * 16 + r;
          a[t][0] = sxu[(kb + kl) * HSTRIDE + m];
          a[t][1] = sxu[(kb + kl) * HSTRIDE + m + 8];
          a[t][2] = sxu[(kb + 4 + kl) * HSTRIDE + m];
          a[t][3] = sxu[(kb + 4 + kl) * HSTRIDE + m + 8];
        }
#pragma unroll
        for (int u = 0; u < 4; u++) {
          int n = nbase + u * 8 + r;
          bb[u] = w2p[(prc + k8 * 4 + kl) * 128 + (n ^ (kl << 2))];
        }
#pragma unroll
        for (int t = 0; t < 2; t++)
#pragma unroll
          for (int u = 0; u < 4; u++)
            mma8(d2[t][u], a[t][0], a[t][1], a[t][2], a[t][3], bb[u].x, bb[u].y);
      }
    }

    // ================= epilogue: y = efeat + silu(D2+b2); LN =================
    float y[2][4][4];
    float s0[2], q0[2], s1[2], q1[2];
#pragma unroll
    for (int t = 0; t < 2; t++) { s0[t] = q0[t] = s1[t] = q1[t] = 0.f; }
#pragma unroll
    for (int t = 0; t < 2; t++) {
      int m = mbase + t * 16 + r;
#pragma unroll
      for (int u = 0; u < 4; u++) {
        int n = nbase + u * 8 + 2 * kl;
        float2 ef0 = *(const float2*)(efeat + (size_t)(e0 + m) * 128 + n);
        float2 ef1 = *(const float2*)(efeat + (size_t)(e0 + m + 8) * 128 + n);
        float v0 = ef0.x + silu_f(d2[t][u][0] + b2v[u][0]);
        float v1 = ef0.y + silu_f(d2[t][u][1] + b2v[u][1]);
        float v2 = ef1.x + silu_f(d2[t][u][2] + b2v[u][0]);
        float v3 = ef1.y + silu_f(d2[t][u][3] + b2v[u][1]);
        y[t][u][0] = v0; y[t][u][1] = v1; y[t][u][2] = v2; y[t][u][3] = v3;
        s0[t] += v0 + v1; q0[t] += v0 * v0 + v1 * v1;
        s1[t] += v2 + v3; q1[t] += v2 * v2 + v3 * v3;
      }
    }
#pragma unroll
    for (int t = 0; t < 2; t++) {
#pragma unroll
      for (int off = 1; off <= 2; off <<= 1) {
        s0[t] += __shfl_xor_sync(0xffffffffu, s0[t], off);
        q0[t] += __shfl_xor_sync(0xffffffffu, q0[t], off);
        s1[t] += __shfl_xor_sync(0xffffffffu, s1[t], off);
        q1[t] += __shfl_xor_sync(0xffffffffu, q1[t], off);
      }
    }
    __syncthreads();   // GEMM2 sxu reads complete
    float2* red = (float2*)sxu;   // [4 nj][128 m]
    if (kl == 0) {
#pragma unroll
      for (int t = 0; t < 2; t++) {
        int m = mbase + t * 16 + r;
        red[nj * 128 + m]     = make_float2(s0[t], q0[t]);
        red[nj * 128 + m + 8] = make_float2(s1[t], q1[t]);
      }
    }
    __syncthreads();
#pragma unroll
    for (int t = 0; t < 2; t++) {
      int m = mbase + t * 16 + r;
      float S0 = 0.f, Q0 = 0.f, S1 = 0.f, Q1 = 0.f;
#pragma unroll
      for (int qd = 0; qd < 4; qd++) {
        float2 v = red[qd * 128 + m];     S0 += v.x; Q0 += v.y;
        float2 w = red[qd * 128 + m + 8]; S1 += w.x; Q1 += w.y;
      }
      float mean0 = S0 * 0.0078125f;
      float var0  = Q0 * 0.0078125f - mean0 * mean0;
      float rs0   = rsqrtf(var0 + 1e-5f);
      float mean1 = S1 * 0.0078125f;
      float var1  = Q1 * 0.0078125f - mean1 * mean1;
      float rs1   = rsqrtf(var1 + 1e-5f);
#pragma unroll
      for (int u = 0; u < 4; u++) {
        int n = nbase + u * 8 + 2 * kl;
        float2 o0, o1;
        o0.x = (y[t][u][0] - mean0) * rs0 * gv[u][0] + btv[u][0];
        o0.y = (y[t][u][1] - mean0) * rs0 * gv[u][1] + btv[u][1];
        o1.x = (y[t][u][2] - mean1) * rs1 * gv[u][0] + btv[u][0];
        o1.y = (y[t][u][3] - mean1) * rs1 * gv[u][1] + btv[u][1];
        *(float2*)(out + (size_t)(e0 + m) * 128 + n)     = o0;
        *(float2*)(out + (size_t)(e0 + m + 8) * 128 + n) = o1;
      }
    }
    // next tile's first __syncthreads orders sxu/red reuse
  }
}

extern "C" void kernel_launch(void* const* d_in, const int* in_sizes, int n_in,
                              void* d_out, int out_size) {
  const float* nodes = (const float*)d_in[0];
  const float* efeat = (const float*)d_in[1];
  const int*   srcI  = (const int*)d_in[2];
  const int*   dstI  = (const int*)d_in[3];
  const float* W1    = (const float*)d_in[4];
  const float* b1    = (const float*)d_in[5];
  const float* W2    = (const float*)d_in[6];
  const float* b2    = (const float*)d_in[7];
  const float* gamma = (const float*)d_in[8];
  const float* beta  = (const float*)d_in[9];
  float* out = (float*)d_out;

  cudaFuncSetAttribute(edge_update_mma6,
                       cudaFuncAttributeMaxDynamicSharedMemorySize, SMEM_BYTES);
  int sms = 148;
  cudaDeviceGetAttribute(&sms, cudaDevAttrMultiProcessorCount, 0);
  if (sms < 1) sms = 148;

  edge_update_mma6<<<sms, THREADS, SMEM_BYTES>>>(
      nodes, efeat, srcI, dstI, W1, b1, W2, b2, gamma, beta, out);
}